// round 16
// baseline (speedup 1.0000x reference)
#include <cuda_runtime.h>
#include <math.h>
#include <stdint.h>

#define Bb 2
#define Ll 384
#define Dd 128
#define NH 8
#define DHSc 16
#define NPC 12            // DHP*3
#define FEAT 1280
#define KSPLIT 10
#define OUTROWS (Bb*Ll)

// ---------------- scratch (no allocations allowed) ----------------
static __device__ __align__(16) float g_qs[Bb*NH*Ll*DHSc];
static __device__ __align__(16) float g_ks[Bb*NH*Ll*DHSc];
static __device__ __align__(16) float g_vs[Bb*NH*Ll*DHSc];
static __device__ __align__(16) float g_qp[Bb*NH*Ll*NPC];
static __device__ __align__(16) float g_kp[Bb*NH*Ll*NPC];
static __device__ __align__(16) float g_vp[Bb*NH*Ll*NPC];
static __device__ __align__(16) float g_qq[Bb*NH*Ll];
static __device__ __align__(16) float g_kk[Bb*NH*Ll];
static __device__ __align__(16) float g_logit[(size_t)Bb*NH*Ll*Ll];  // pre-logit (qk terms, scaled)
static __device__ __align__(16) float g_bias[(size_t)Bb*Ll*Ll*NH];   // [bi][j][n], scaled
static __device__ __align__(16) float g_attn[(size_t)Bb*Ll*NH*Ll];   // [bi][n][j]
static __device__ __align__(16) float g_feat[Bb*Ll*FEAT];
static __device__ __align__(16) float g_part[KSPLIT*OUTROWS*Dd];

// ---------------- kernel 1: projections, 8 i-rows per block ----------------
__global__ __launch_bounds__(256) void proj_kernel(
    const float* __restrict__ x, const float* __restrict__ r, const float* __restrict__ t,
    const float* __restrict__ Wqs, const float* __restrict__ Wks, const float* __restrict__ Wvs,
    const float* __restrict__ Wqp, const float* __restrict__ Wkp, const float* __restrict__ Wvp)
{
    int bi0 = blockIdx.x * 8;
    int b = bi0 / Ll, i0 = bi0 % Ll;
    int tid = threadIdx.x;
    __shared__ __align__(16) float xs[8][Dd];
    __shared__ float rsm[8][9], tsm[8][3];
    __shared__ float xp[3][8][96];
    __shared__ float sq[2][8][96];
    {
        int row = tid >> 5, dq = tid & 31;
        *(float4*)&xs[row][dq * 4] = *(const float4*)&x[(size_t)(bi0 + row) * Dd + dq * 4];
    }
    if (tid < 72) rsm[tid / 9][tid % 9] = r[(bi0 + tid / 9) * 9 + tid % 9];
    else if (tid < 96) { int m = tid - 72; tsm[m / 3][m % 3] = t[(bi0 + m / 3) * 3 + m % 3]; }
    __syncthreads();

    float acc[8];
    {
        const float* W = (tid < 128) ? Wqs : Wks;
        int c = tid & 127;
        #pragma unroll
        for (int rr = 0; rr < 8; rr++) acc[rr] = 0.f;
        #pragma unroll 4
        for (int k = 0; k < Dd; k++) {
            float w = W[k * Dd + c];
            #pragma unroll
            for (int rr = 0; rr < 8; rr++) acc[rr] += xs[rr][k] * w;
        }
        int n = c >> 4, d = c & 15;
        float* dst = (tid < 128) ? g_qs : g_ks;
        #pragma unroll
        for (int rr = 0; rr < 8; rr++)
            dst[((b * NH + n) * Ll + i0 + rr) * DHSc + d] = acc[rr];
    }
    {
        #pragma unroll
        for (int rr = 0; rr < 8; rr++) acc[rr] = 0.f;
        if (tid < 128) {
            int c = tid;
            #pragma unroll 4
            for (int k = 0; k < Dd; k++) {
                float w = Wvs[k * Dd + c];
                #pragma unroll
                for (int rr = 0; rr < 8; rr++) acc[rr] += xs[rr][k] * w;
            }
            int n = c >> 4, d = c & 15;
            #pragma unroll
            for (int rr = 0; rr < 8; rr++)
                g_vs[((b * NH + n) * Ll + i0 + rr) * DHSc + d] = acc[rr];
        } else if (tid < 224) {
            int c = tid - 128;
            #pragma unroll 4
            for (int k = 0; k < Dd; k++) {
                float w = Wqp[k * 96 + c];
                #pragma unroll
                for (int rr = 0; rr < 8; rr++) acc[rr] += xs[rr][k] * w;
            }
            #pragma unroll
            for (int rr = 0; rr < 8; rr++) xp[0][rr][c] = acc[rr];
        }
    }
    {
        #pragma unroll
        for (int rr = 0; rr < 8; rr++) acc[rr] = 0.f;
        if (tid < 96) {
            #pragma unroll 4
            for (int k = 0; k < Dd; k++) {
                float w = Wkp[k * 96 + tid];
                #pragma unroll
                for (int rr = 0; rr < 8; rr++) acc[rr] += xs[rr][k] * w;
            }
            #pragma unroll
            for (int rr = 0; rr < 8; rr++) xp[1][rr][tid] = acc[rr];
        } else if (tid < 192) {
            int c = tid - 96;
            #pragma unroll 4
            for (int k = 0; k < Dd; k++) {
                float w = Wvp[k * 96 + c];
                #pragma unroll
                for (int rr = 0; rr < 8; rr++) acc[rr] += xs[rr][k] * w;
            }
            #pragma unroll
            for (int rr = 0; rr < 8; rr++) xp[2][rr][c] = acc[rr];
        }
    }
    __syncthreads();
    for (int task = tid; task < 2304; task += 256) {
        int mat = task / 768, rem = task % 768;
        int row = rem / 96, pc = rem % 96;
        int n = pc / 12, pcc = pc % 12, cc = pcc % 3;
        const float* xb = &xp[mat][row][pc - cc];
        float v = xb[0] * rsm[row][cc] + xb[1] * rsm[row][3 + cc]
                + xb[2] * rsm[row][6 + cc] + tsm[row][cc];
        float* dst = (mat == 0) ? g_qp : (mat == 1) ? g_kp : g_vp;
        dst[((b * NH + n) * Ll + i0 + row) * NPC + pcc] = v;
        if (mat < 2) sq[mat][row][pc] = v * v;
    }
    __syncthreads();
    if (tid < 128) {
        int mat = tid >> 6, rem = tid & 63, row = rem >> 3, n = rem & 7;
        float s = 0.f;
        #pragma unroll
        for (int m = 0; m < 12; m++) s += sq[mat][row][n * 12 + m];
        (mat == 0 ? g_qq : g_kk)[(b * NH + n) * Ll + i0 + row] = s;
    }
}

// ---------------- kernel 2: pre-logit (scalar qk + point term), grid (16, 6, 8) ----------------
__global__ __launch_bounds__(256) void qk_kernel(const float* __restrict__ gamma)
{
    int bn = blockIdx.x;
    int j0 = blockIdx.y * 64;
    int i0 = blockIdx.z * 48;
    int tid = threadIdx.x;
    __shared__ __align__(16) float qs_s[48 * DHSc];
    __shared__ __align__(16) float qp_s[48 * NPC];
    __shared__ float qq_s[48];

    {
        const float4* src = (const float4*)&g_qs[((size_t)bn * Ll + i0) * DHSc];
        float4* dst = (float4*)qs_s;
        if (tid < 48 * DHSc / 4) dst[tid] = src[tid];
    }
    {
        const float4* src = (const float4*)&g_qp[((size_t)bn * Ll + i0) * NPC];
        float4* dst = (float4*)qp_s;
        if (tid < 48 * NPC / 4) dst[tid] = src[tid];
    }
    if (tid < 48) qq_s[tid] = g_qq[bn * Ll + i0 + tid];
    __syncthreads();

    int j = j0 + (tid & 63);
    int ig = tid >> 6;
    float g2 = 0.07216878364870322f * gamma[bn & 7];
    const float4* kr = (const float4*)&g_ks[((size_t)bn * Ll + j) * DHSc];
    float4 k0 = kr[0], k1 = kr[1], k2 = kr[2], k3 = kr[3];
    const float4* kpr = (const float4*)&g_kp[((size_t)bn * Ll + j) * NPC];
    float4 p0 = kpr[0], p1 = kpr[1], p2 = kpr[2];
    float kkv = g_kk[bn * Ll + j];
    float* outb = &g_logit[((size_t)bn * Ll + i0) * Ll + j];
    #pragma unroll 4
    for (int ii = 0; ii < 12; ii++) {
        int il = ig * 12 + ii;
        const float4* qr = (const float4*)&qs_s[il * DHSc];
        float4 q0 = qr[0], q1 = qr[1], q2 = qr[2], q3 = qr[3];
        float s = q0.x*k0.x + q0.y*k0.y + q0.z*k0.z + q0.w*k0.w
                + q1.x*k1.x + q1.y*k1.y + q1.z*k1.z + q1.w*k1.w
                + q2.x*k2.x + q2.y*k2.y + q2.z*k2.z + q2.w*k2.w
                + q3.x*k3.x + q3.y*k3.y + q3.z*k3.z + q3.w*k3.w;
        const float4* qpr = (const float4*)&qp_s[il * NPC];
        float4 a0 = qpr[0], a1 = qpr[1], a2 = qpr[2];
        float cr = a0.x*p0.x + a0.y*p0.y + a0.z*p0.z + a0.w*p0.w
                 + a1.x*p1.x + a1.y*p1.y + a1.z*p1.z + a1.w*p1.w
                 + a2.x*p2.x + a2.y*p2.y + a2.z*p2.z + a2.w*p2.w;
        float d2 = qq_s[il] + kkv - 2.f * cr;
        outb[(size_t)il * Ll] = 0.14433756729740643f * s - g2 * d2;
    }
}

// ---------------- kernel 3: bias = 0.577 * e_row @ Wb, thread-per-row, per batch ----------------
__global__ __launch_bounds__(256) void bias_kernel(
    const float* __restrict__ e, const float* __restrict__ Wb, int b)
{
    __shared__ __align__(16) float wbs[Dd * NH];   // [k][n]
    int tid = threadIdx.x;
    ((float4*)wbs)[tid] = ((const float4*)Wb)[tid];
    __syncthreads();
    size_t row = (size_t)b * Ll * Ll + (size_t)blockIdx.x * 256 + tid;   // (bi*384 + j)
    const float4* er = (const float4*)(e + row * Dd);
    float acc0=0.f, acc1=0.f, acc2=0.f, acc3=0.f, acc4=0.f, acc5=0.f, acc6=0.f, acc7=0.f;
    #pragma unroll
    for (int kq = 0; kq < 32; kq++) {
        float4 ev = er[kq];
        const float* wb = &wbs[kq * 32];
        float4 ax = *(const float4*)&wb[0],  ay = *(const float4*)&wb[4];
        float4 bx = *(const float4*)&wb[8],  by = *(const float4*)&wb[12];
        float4 cx = *(const float4*)&wb[16], cy = *(const float4*)&wb[20];
        float4 dx = *(const float4*)&wb[24], dy = *(const float4*)&wb[28];
        acc0 += ev.x*ax.x + ev.y*bx.x + ev.z*cx.x + ev.w*dx.x;
        acc1 += ev.x*ax.y + ev.y*bx.y + ev.z*cx.y + ev.w*dx.y;
        acc2 += ev.x*ax.z + ev.y*bx.z + ev.z*cx.z + ev.w*dx.z;
        acc3 += ev.x*ax.w + ev.y*bx.w + ev.z*cx.w + ev.w*dx.w;
        acc4 += ev.x*ay.x + ev.y*by.x + ev.z*cy.x + ev.w*dy.x;
        acc5 += ev.x*ay.y + ev.y*by.y + ev.z*cy.y + ev.w*dy.y;
        acc6 += ev.x*ay.z + ev.y*by.z + ev.z*cy.z + ev.w*dy.z;
        acc7 += ev.x*ay.w + ev.y*by.w + ev.z*cy.w + ev.w*dy.w;
    }
    const float C = 0.5773502691896258f;
    *(float4*)&g_bias[row * NH]     = make_float4(C*acc0, C*acc1, C*acc2, C*acc3);
    *(float4*)&g_bias[row * NH + 4] = make_float4(C*acc4, C*acc5, C*acc6, C*acc7);
}

// ---------------- kernel 4: logits + softmax + out_pair (attn @ e), per batch ----------------
__global__ __launch_bounds__(256) void midpair_kernel(const float* __restrict__ e, int b)
{
    int bi = b * Ll + blockIdx.x;
    int i = blockIdx.x;
    int tid = threadIdx.x;
    int warp = tid >> 5, lane = tid & 31;

    __shared__ __align__(16) float attn_s[NH * Ll];   // 12KB
    __shared__ __align__(16) float pool[4096];        // bias tile (3072), then reduce tree

    // bias tile [j][n]
    {
        const float4* src = (const float4*)&g_bias[(size_t)bi * Ll * NH];
        float4* dst = (float4*)pool;
        for (int m = tid; m < Ll * NH / 4; m += 256) dst[m] = src[m];
    }
    __syncthreads();

    // full logits
    for (int m = tid; m < NH * Ll; m += 256) {
        int n = m / Ll, j = m - n * Ll;
        attn_s[m] = g_logit[((size_t)(b * NH + n) * Ll + i) * Ll + j] + pool[j * NH + n];
    }
    __syncthreads();

    // softmax: warp = head; write normalized attn to smem and g_attn
    {
        float* rowp = &attn_s[warp * Ll];
        float mx = -1e30f;
        for (int j = lane; j < Ll; j += 32) mx = fmaxf(mx, rowp[j]);
        #pragma unroll
        for (int off = 16; off > 0; off >>= 1)
            mx = fmaxf(mx, __shfl_xor_sync(0xffffffffu, mx, off));
        float sum = 0.f;
        for (int j = lane; j < Ll; j += 32) {
            float ex = __expf(rowp[j] - mx);
            rowp[j] = ex;
            sum += ex;
        }
        #pragma unroll
        for (int off = 16; off > 0; off >>= 1)
            sum += __shfl_xor_sync(0xffffffffu, sum, off);
        float inv = 1.f / sum;
        float* ga = &g_attn[(size_t)bi * NH * Ll + warp * Ll];
        for (int j = lane; j < Ll; j += 32) {
            float a = rowp[j] * inv;
            rowp[j] = a;
            ga[j] = a;
        }
    }
    __syncthreads();

    // out_pair = attn @ e : warp owns j-residues, lane owns d-quarter
    float acc[NH][4];
    #pragma unroll
    for (int n = 0; n < NH; n++) { acc[n][0]=0.f; acc[n][1]=0.f; acc[n][2]=0.f; acc[n][3]=0.f; }
    const float4* eb = (const float4*)(e + (size_t)bi * Ll * Dd);
    #pragma unroll 4
    for (int it = 0; it < Ll / 8; it++) {
        int j = warp + it * 8;
        float4 ev = eb[j * 32 + lane];
        #pragma unroll
        for (int n = 0; n < NH; n++) {
            float p = attn_s[n * Ll + j];
            acc[n][0] += p * ev.x; acc[n][1] += p * ev.y;
            acc[n][2] += p * ev.z; acc[n][3] += p * ev.w;
        }
    }
    __syncthreads();   // attn reads done; pool becomes reduce tree

    #pragma unroll
    for (int stride = 4; stride >= 1; stride >>= 1) {
        if (warp >= stride && warp < 2 * stride) {
            float* dstb = &pool[(warp - stride) * 1024];
            #pragma unroll
            for (int n = 0; n < NH; n++)
                *(float4*)&dstb[n * 128 + lane * 4] =
                    make_float4(acc[n][0], acc[n][1], acc[n][2], acc[n][3]);
        }
        __syncthreads();
        if (warp < stride) {
            const float* srcb = &pool[warp * 1024];
            #pragma unroll
            for (int n = 0; n < NH; n++) {
                float4 v = *(const float4*)&srcb[n * 128 + lane * 4];
                acc[n][0] += v.x; acc[n][1] += v.y; acc[n][2] += v.z; acc[n][3] += v.w;
            }
        }
        __syncthreads();
    }
    if (warp == 0) {
        float* feat = &g_feat[bi * FEAT];
        #pragma unroll
        for (int n = 0; n < NH; n++)
            *(float4*)&feat[128 + n * 128 + lane * 4] =
                make_float4(acc[n][0], acc[n][1], acc[n][2], acc[n][3]);
    }
}

// ---------------- kernel 5: out_scalar + op + rotation/norm, grid (16, 6) ----------------
#define IT 64
__global__ __launch_bounds__(224) void sv_kernel(
    const float* __restrict__ r, const float* __restrict__ t)
{
    int bn = blockIdx.x;
    int b = bn >> 3, n = bn & 7;
    int i0 = blockIdx.y * IT;
    int tid = threadIdx.x;
    int ig = tid & 31;        // i-group: rows ig*2, ig*2+1
    int cq = tid >> 5;        // col-quad 0..6 (0-3 scalar d, 4-6 point pc)

    __shared__ __align__(16) float attn_t[64 * IT];   // [j][i], 16KB
    __shared__ __align__(16) float Bsm[64 * 32];      // [j][32] (16 vs + 12 vp + pad), 8KB
    __shared__ __align__(16) float rt_s[IT * 12];     // r(9)+t(3) per i
    __shared__ __align__(16) float op_s[IT * 12];
    __shared__ float opl2[IT * 12];

    for (int m = tid; m < IT * 12; m += 224) {
        int ii = m / 12, c = m % 12;
        rt_s[m] = (c < 9) ? r[(size_t)(b * Ll + i0 + ii) * 9 + c]
                          : t[(size_t)(b * Ll + i0 + ii) * 3 + (c - 9)];
    }

    float a0[4] = {0.f, 0.f, 0.f, 0.f};
    float a1[4] = {0.f, 0.f, 0.f, 0.f};

    for (int c6 = 0; c6 < 6; c6++) {
        int j0 = c6 * 64;
        __syncthreads();
        for (int m = tid; m < IT * 16; m += 224) {
            int ii = m & (IT - 1), jq = m >> 6;
            float4 v = *(const float4*)&g_attn[
                (size_t)(b * Ll + i0 + ii) * (NH * Ll) + n * Ll + j0 + jq * 4];
            attn_t[(jq * 4 + 0) * IT + ii] = v.x;
            attn_t[(jq * 4 + 1) * IT + ii] = v.y;
            attn_t[(jq * 4 + 2) * IT + ii] = v.z;
            attn_t[(jq * 4 + 3) * IT + ii] = v.w;
        }
        for (int m = tid; m < 256; m += 224) {
            int j = m >> 2, dq = m & 3;
            *(float4*)&Bsm[j * 32 + dq * 4] =
                *(const float4*)&g_vs[((size_t)bn * Ll + j0 + j) * DHSc + dq * 4];
        }
        for (int m = tid; m < 192; m += 224) {
            int j = m / 3, dq = m % 3;
            *(float4*)&Bsm[j * 32 + 16 + dq * 4] =
                *(const float4*)&g_vp[((size_t)bn * Ll + j0 + j) * NPC + dq * 4];
        }
        __syncthreads();
        #pragma unroll 4
        for (int j = 0; j < 64; j++) {
            float2 av = *(const float2*)&attn_t[j * IT + ig * 2];
            float4 bv = *(const float4*)&Bsm[j * 32 + cq * 4];
            a0[0] += av.x * bv.x; a0[1] += av.x * bv.y; a0[2] += av.x * bv.z; a0[3] += av.x * bv.w;
            a1[0] += av.y * bv.x; a1[1] += av.y * bv.y; a1[2] += av.y * bv.z; a1[3] += av.y * bv.w;
        }
    }
    __syncthreads();

    if (cq < 4) {
        size_t base0 = (size_t)(b * Ll + i0 + ig * 2) * FEAT + n * DHSc + cq * 4;
        *(float4*)&g_feat[base0]        = make_float4(a0[0], a0[1], a0[2], a0[3]);
        *(float4*)&g_feat[base0 + FEAT] = make_float4(a1[0], a1[1], a1[2], a1[3]);
    } else {
        int pc = (cq - 4) * 4;
        *(float4*)&op_s[(ig * 2 + 0) * 12 + pc] = make_float4(a0[0], a0[1], a0[2], a0[3]);
        *(float4*)&op_s[(ig * 2 + 1) * 12 + pc] = make_float4(a1[0], a1[1], a1[2], a1[3]);
    }
    __syncthreads();

    for (int m = tid; m < IT * 12; m += 224) {
        int ii = m / 12, pc = m % 12;
        int p3 = (pc / 3) * 3, c = pc % 3;
        const float* ob = &op_s[ii * 12 + p3];
        const float* rr = &rt_s[ii * 12];
        float v = (ob[0] - rr[9])  * rr[c * 3 + 0]
                + (ob[1] - rr[10]) * rr[c * 3 + 1]
                + (ob[2] - rr[11]) * rr[c * 3 + 2];
        g_feat[(size_t)(b * Ll + i0 + ii) * FEAT + 1152 + n * 12 + pc] = v;
        opl2[m] = v * v;
    }
    __syncthreads();
    for (int m = tid; m < IT * 4; m += 224) {
        int ii = m >> 2, p = m & 3;
        g_feat[(size_t)(b * Ll + i0 + ii) * FEAT + 1248 + n * 4 + p] =
            sqrtf(opl2[ii * 12 + p * 3] + opl2[ii * 12 + p * 3 + 1] + opl2[ii * 12 + p * 3 + 2]);
    }
}

// ---------------- kernel 6a: partial out GEMM (k-split), 4 rows/thread ----------------
#define TMR 32
#define KC 64
__global__ __launch_bounds__(256) void out_part_kernel(const float* __restrict__ Wo)
{
    int row0 = blockIdx.x * TMR;
    int kbase = blockIdx.y * (FEAT / KSPLIT);
    int tid = threadIdx.x;
    int tx = tid & 31;
    int ty = tid >> 5;       // 0..7 → rows ty*4 .. ty*4+3
    __shared__ __align__(16) float As[TMR * KC];   // 8KB
    __shared__ __align__(16) float Bs[KC * Dd];    // 32KB
    float a0[4] = {0.f,0.f,0.f,0.f};
    float a1[4] = {0.f,0.f,0.f,0.f};
    float a2[4] = {0.f,0.f,0.f,0.f};
    float a3[4] = {0.f,0.f,0.f,0.f};
    #pragma unroll
    for (int tile = 0; tile < (FEAT / KSPLIT) / KC; tile++) {
        int k0 = kbase + tile * KC;
        #pragma unroll
        for (int h = 0; h < 2; h++) {
            int m = tid + h * 256;
            int rr = m >> 4, q = m & 15;
            *(float4*)&As[rr * KC + q * 4] =
                *(const float4*)&g_feat[(row0 + rr) * FEAT + k0 + q * 4];
        }
        {
            const float4* wsrc = (const float4*)(Wo + (size_t)k0 * Dd);
            float4* bdst = (float4*)Bs;
            #pragma unroll
            for (int m = 0; m < 8; m++) bdst[tid + m * 256] = wsrc[tid + m * 256];
        }
        __syncthreads();
        #pragma unroll 4
        for (int kk = 0; kk < KC; kk++) {
            float av0 = As[(ty * 4 + 0) * KC + kk];
            float av1 = As[(ty * 4 + 1) * KC + kk];
            float av2 = As[(ty * 4 + 2) * KC + kk];
            float av3 = As[(ty * 4 + 3) * KC + kk];
            float4 bv = *(const float4*)&Bs[kk * Dd + tx * 4];
            a0[0] += av0 * bv.x; a0[1] += av0 * bv.y; a0[2] += av0 * bv.z; a0[3] += av0 * bv.w;
            a1[0] += av1 * bv.x; a1[1] += av1 * bv.y; a1[2] += av1 * bv.z; a1[3] += av1 * bv.w;
            a2[0] += av2 * bv.x; a2[1] += av2 * bv.y; a2[2] += av2 * bv.z; a2[3] += av2 * bv.w;
            a3[0] += av3 * bv.x; a3[1] += av3 * bv.y; a3[2] += av3 * bv.z; a3[3] += av3 * bv.w;
        }
        __syncthreads();
    }
    size_t base = (size_t)blockIdx.y * OUTROWS * Dd;
    *(float4*)&g_part[base + (size_t)(row0 + ty * 4 + 0) * Dd + tx * 4] =
        make_float4(a0[0], a0[1], a0[2], a0[3]);
    *(float4*)&g_part[base + (size_t)(row0 + ty * 4 + 1) * Dd + tx * 4] =
        make_float4(a1[0], a1[1], a1[2], a1[3]);
    *(float4*)&g_part[base + (size_t)(row0 + ty * 4 + 2) * Dd + tx * 4] =
        make_float4(a2[0], a2[1], a2[2], a2[3]);
    *(float4*)&g_part[base + (size_t)(row0 + ty * 4 + 3) * Dd + tx * 4] =
        make_float4(a3[0], a3[1], a3[2], a3[3]);
}

// ---------------- kernel 6b: reduce partials + bias ----------------
__global__ __launch_bounds__(256) void out_reduce_kernel(
    const float* __restrict__ bo, float* __restrict__ out)
{
    int idx = blockIdx.x * 256 + threadIdx.x;
    int c = idx & (Dd - 1);
    float a = bo[c];
    #pragma unroll
    for (int s = 0; s < KSPLIT; s++) a += g_part[s * (OUTROWS * Dd) + idx];
    out[idx] = a;
}

// ---------------- launch ----------------
extern "C" void kernel_launch(void* const* d_in, const int* in_sizes, int n_in,
                              void* d_out, int out_size) {
    const float* x     = (const float*)d_in[0];
    const float* e     = (const float*)d_in[1];
    const float* r     = (const float*)d_in[2];
    const float* t     = (const float*)d_in[3];
    const float* Wqs   = (const float*)d_in[4];
    const float* Wks   = (const float*)d_in[5];
    const float* Wvs   = (const float*)d_in[6];
    const float* Wb    = (const float*)d_in[7];
    const float* Wqp   = (const float*)d_in[8];
    const float* Wkp   = (const float*)d_in[9];
    const float* Wvp   = (const float*)d_in[10];
    const float* gamma = (const float*)d_in[11];
    const float* Wo    = (const float*)d_in[12];
    const float* bo    = (const float*)d_in[13];
    float* out = (float*)d_out;

    proj_kernel<<<(Bb * Ll) / 8, 256>>>(x, r, t, Wqs, Wks, Wvs, Wqp, Wkp, Wvp);
    qk_kernel<<<dim3(Bb * NH, Ll / 64, 8), 256>>>(gamma);
    for (int b = 0; b < Bb; b++) {
        bias_kernel<<<(Ll * Ll) / 256, 256>>>(e, Wb, b);
        midpair_kernel<<<Ll, 256>>>(e, b);
    }
    sv_kernel<<<dim3(Bb * NH, Ll / IT), 224>>>(r, t);
    out_part_kernel<<<dim3((Bb * Ll) / TMR, KSPLIT), 256>>>(Wo);
    out_reduce_kernel<<<(OUTROWS * Dd) / 256, 256>>>(bo, out);
}

// round 17
// speedup vs baseline: 1.1511x; 1.1511x over previous
#include <cuda_runtime.h>
#include <math.h>
#include <stdint.h>

#define Bb 2
#define Ll 384
#define Dd 128
#define NH 8
#define DHSc 16
#define NPC 12            // DHP*3
#define FEAT 1280
#define KSPLIT 10
#define OUTROWS (Bb*Ll)
#define QKBLKS 768        // qk sub-grid size inside fused qkbias kernel

// ---------------- scratch (no allocations allowed) ----------------
static __device__ __align__(16) float g_qs[Bb*NH*Ll*DHSc];
static __device__ __align__(16) float g_ks[Bb*NH*Ll*DHSc];
static __device__ __align__(16) float g_vs[Bb*NH*Ll*DHSc];
static __device__ __align__(16) float g_qp[Bb*NH*Ll*NPC];
static __device__ __align__(16) float g_kp[Bb*NH*Ll*NPC];
static __device__ __align__(16) float g_vp[Bb*NH*Ll*NPC];
static __device__ __align__(16) float g_qq[Bb*NH*Ll];
static __device__ __align__(16) float g_kk[Bb*NH*Ll];
static __device__ __align__(16) float g_logit[(size_t)Bb*NH*Ll*Ll];  // pre-logit (qk terms, scaled)
static __device__ __align__(16) float g_bias[(size_t)Bb*Ll*Ll*NH];   // [bi][j][n], scaled
static __device__ __align__(16) float g_attn[(size_t)Bb*Ll*NH*Ll];   // [bi][n][j]
static __device__ __align__(16) float g_feat[Bb*Ll*FEAT];
static __device__ __align__(16) float g_part[KSPLIT*OUTROWS*Dd];

// ---------------- kernel 1: projections, 8 i-rows per block ----------------
__global__ __launch_bounds__(256) void proj_kernel(
    const float* __restrict__ x, const float* __restrict__ r, const float* __restrict__ t,
    const float* __restrict__ Wqs, const float* __restrict__ Wks, const float* __restrict__ Wvs,
    const float* __restrict__ Wqp, const float* __restrict__ Wkp, const float* __restrict__ Wvp)
{
    int bi0 = blockIdx.x * 8;
    int b = bi0 / Ll, i0 = bi0 % Ll;
    int tid = threadIdx.x;
    __shared__ __align__(16) float xs[8][Dd];
    __shared__ float rsm[8][9], tsm[8][3];
    __shared__ float xp[3][8][96];
    __shared__ float sq[2][8][96];
    {
        int row = tid >> 5, dq = tid & 31;
        *(float4*)&xs[row][dq * 4] = *(const float4*)&x[(size_t)(bi0 + row) * Dd + dq * 4];
    }
    if (tid < 72) rsm[tid / 9][tid % 9] = r[(bi0 + tid / 9) * 9 + tid % 9];
    else if (tid < 96) { int m = tid - 72; tsm[m / 3][m % 3] = t[(bi0 + m / 3) * 3 + m % 3]; }
    __syncthreads();

    float acc[8];
    {
        const float* W = (tid < 128) ? Wqs : Wks;
        int c = tid & 127;
        #pragma unroll
        for (int rr = 0; rr < 8; rr++) acc[rr] = 0.f;
        #pragma unroll 4
        for (int k = 0; k < Dd; k++) {
            float w = W[k * Dd + c];
            #pragma unroll
            for (int rr = 0; rr < 8; rr++) acc[rr] += xs[rr][k] * w;
        }
        int n = c >> 4, d = c & 15;
        float* dst = (tid < 128) ? g_qs : g_ks;
        #pragma unroll
        for (int rr = 0; rr < 8; rr++)
            dst[((b * NH + n) * Ll + i0 + rr) * DHSc + d] = acc[rr];
    }
    {
        #pragma unroll
        for (int rr = 0; rr < 8; rr++) acc[rr] = 0.f;
        if (tid < 128) {
            int c = tid;
            #pragma unroll 4
            for (int k = 0; k < Dd; k++) {
                float w = Wvs[k * Dd + c];
                #pragma unroll
                for (int rr = 0; rr < 8; rr++) acc[rr] += xs[rr][k] * w;
            }
            int n = c >> 4, d = c & 15;
            #pragma unroll
            for (int rr = 0; rr < 8; rr++)
                g_vs[((b * NH + n) * Ll + i0 + rr) * DHSc + d] = acc[rr];
        } else if (tid < 224) {
            int c = tid - 128;
            #pragma unroll 4
            for (int k = 0; k < Dd; k++) {
                float w = Wqp[k * 96 + c];
                #pragma unroll
                for (int rr = 0; rr < 8; rr++) acc[rr] += xs[rr][k] * w;
            }
            #pragma unroll
            for (int rr = 0; rr < 8; rr++) xp[0][rr][c] = acc[rr];
        }
    }
    {
        #pragma unroll
        for (int rr = 0; rr < 8; rr++) acc[rr] = 0.f;
        if (tid < 96) {
            #pragma unroll 4
            for (int k = 0; k < Dd; k++) {
                float w = Wkp[k * 96 + tid];
                #pragma unroll
                for (int rr = 0; rr < 8; rr++) acc[rr] += xs[rr][k] * w;
            }
            #pragma unroll
            for (int rr = 0; rr < 8; rr++) xp[1][rr][tid] = acc[rr];
        } else if (tid < 192) {
            int c = tid - 96;
            #pragma unroll 4
            for (int k = 0; k < Dd; k++) {
                float w = Wvp[k * 96 + c];
                #pragma unroll
                for (int rr = 0; rr < 8; rr++) acc[rr] += xs[rr][k] * w;
            }
            #pragma unroll
            for (int rr = 0; rr < 8; rr++) xp[2][rr][c] = acc[rr];
        }
    }
    __syncthreads();
    for (int task = tid; task < 2304; task += 256) {
        int mat = task / 768, rem = task % 768;
        int row = rem / 96, pc = rem % 96;
        int n = pc / 12, pcc = pc % 12, cc = pcc % 3;
        const float* xb = &xp[mat][row][pc - cc];
        float v = xb[0] * rsm[row][cc] + xb[1] * rsm[row][3 + cc]
                + xb[2] * rsm[row][6 + cc] + tsm[row][cc];
        float* dst = (mat == 0) ? g_qp : (mat == 1) ? g_kp : g_vp;
        dst[((b * NH + n) * Ll + i0 + row) * NPC + pcc] = v;
        if (mat < 2) sq[mat][row][pc] = v * v;
    }
    __syncthreads();
    if (tid < 128) {
        int mat = tid >> 6, rem = tid & 63, row = rem >> 3, n = rem & 7;
        float s = 0.f;
        #pragma unroll
        for (int m = 0; m < 12; m++) s += sq[mat][row][n * 12 + m];
        (mat == 0 ? g_qq : g_kk)[(b * NH + n) * Ll + i0 + row] = s;
    }
}

// ---------------- kernel 2: fused qk (blocks 0..767) + bias (blocks 768..1919) ----------------
__global__ __launch_bounds__(256) void qkbias_kernel(
    const float* __restrict__ gamma, const float* __restrict__ e,
    const float* __restrict__ Wb)
{
    int tid = threadIdx.x;
    if (blockIdx.x < QKBLKS) {
        // ---- qk part: pre-logit (scalar qk + point term) ----
        int id = blockIdx.x;
        int bn = id & 15;
        int j0 = ((id >> 4) % 6) * 64;
        int i0 = (id / 96) * 48;
        __shared__ __align__(16) float qs_s[48 * DHSc];
        __shared__ __align__(16) float qp_s[48 * NPC];
        __shared__ float qq_s[48];

        {
            const float4* src = (const float4*)&g_qs[((size_t)bn * Ll + i0) * DHSc];
            float4* dst = (float4*)qs_s;
            if (tid < 48 * DHSc / 4) dst[tid] = src[tid];
        }
        {
            const float4* src = (const float4*)&g_qp[((size_t)bn * Ll + i0) * NPC];
            float4* dst = (float4*)qp_s;
            if (tid < 48 * NPC / 4) dst[tid] = src[tid];
        }
        if (tid < 48) qq_s[tid] = g_qq[bn * Ll + i0 + tid];
        __syncthreads();

        int j = j0 + (tid & 63);
        int ig = tid >> 6;
        float g2 = 0.07216878364870322f * gamma[bn & 7];
        const float4* kr = (const float4*)&g_ks[((size_t)bn * Ll + j) * DHSc];
        float4 k0 = kr[0], k1 = kr[1], k2 = kr[2], k3 = kr[3];
        const float4* kpr = (const float4*)&g_kp[((size_t)bn * Ll + j) * NPC];
        float4 p0 = kpr[0], p1 = kpr[1], p2 = kpr[2];
        float kkv = g_kk[bn * Ll + j];
        float* outb = &g_logit[((size_t)bn * Ll + i0) * Ll + j];
        #pragma unroll 4
        for (int ii = 0; ii < 12; ii++) {
            int il = ig * 12 + ii;
            const float4* qr = (const float4*)&qs_s[il * DHSc];
            float4 q0 = qr[0], q1 = qr[1], q2 = qr[2], q3 = qr[3];
            float s = q0.x*k0.x + q0.y*k0.y + q0.z*k0.z + q0.w*k0.w
                    + q1.x*k1.x + q1.y*k1.y + q1.z*k1.z + q1.w*k1.w
                    + q2.x*k2.x + q2.y*k2.y + q2.z*k2.z + q2.w*k2.w
                    + q3.x*k3.x + q3.y*k3.y + q3.z*k3.z + q3.w*k3.w;
            const float4* qpr = (const float4*)&qp_s[il * NPC];
            float4 a0 = qpr[0], a1 = qpr[1], a2 = qpr[2];
            float cr = a0.x*p0.x + a0.y*p0.y + a0.z*p0.z + a0.w*p0.w
                     + a1.x*p1.x + a1.y*p1.y + a1.z*p1.z + a1.w*p1.w
                     + a2.x*p2.x + a2.y*p2.y + a2.z*p2.z + a2.w*p2.w;
            float d2 = qq_s[il] + kkv - 2.f * cr;
            outb[(size_t)il * Ll] = 0.14433756729740643f * s - g2 * d2;
        }
    } else {
        // ---- bias part: 0.577 * e_row @ Wb, thread-per-row ----
        __shared__ __align__(16) float wbs[Dd * NH];   // [k][n]
        ((float4*)wbs)[tid] = ((const float4*)Wb)[tid];
        __syncthreads();
        size_t row = (size_t)(blockIdx.x - QKBLKS) * 256 + tid;   // (bi*384 + j)
        const float4* er = (const float4*)(e + row * Dd);
        float acc0=0.f, acc1=0.f, acc2=0.f, acc3=0.f, acc4=0.f, acc5=0.f, acc6=0.f, acc7=0.f;
        #pragma unroll
        for (int kq = 0; kq < 32; kq++) {
            float4 ev = er[kq];
            const float* wb = &wbs[kq * 32];
            float4 ax = *(const float4*)&wb[0],  ay = *(const float4*)&wb[4];
            float4 bx = *(const float4*)&wb[8],  by = *(const float4*)&wb[12];
            float4 cx = *(const float4*)&wb[16], cy = *(const float4*)&wb[20];
            float4 dx = *(const float4*)&wb[24], dy = *(const float4*)&wb[28];
            acc0 += ev.x*ax.x + ev.y*bx.x + ev.z*cx.x + ev.w*dx.x;
            acc1 += ev.x*ax.y + ev.y*bx.y + ev.z*cx.y + ev.w*dx.y;
            acc2 += ev.x*ax.z + ev.y*bx.z + ev.z*cx.z + ev.w*dx.z;
            acc3 += ev.x*ax.w + ev.y*bx.w + ev.z*cx.w + ev.w*dx.w;
            acc4 += ev.x*ay.x + ev.y*by.x + ev.z*cy.x + ev.w*dy.x;
            acc5 += ev.x*ay.y + ev.y*by.y + ev.z*cy.y + ev.w*dy.y;
            acc6 += ev.x*ay.z + ev.y*by.z + ev.z*cy.z + ev.w*dy.z;
            acc7 += ev.x*ay.w + ev.y*by.w + ev.z*cy.w + ev.w*dy.w;
        }
        const float C = 0.5773502691896258f;
        *(float4*)&g_bias[row * NH]     = make_float4(C*acc0, C*acc1, C*acc2, C*acc3);
        *(float4*)&g_bias[row * NH + 4] = make_float4(C*acc4, C*acc5, C*acc6, C*acc7);
    }
}

// ---------------- kernel 3: logits + softmax + out_pair (attn @ e) ----------------
__global__ __launch_bounds__(256) void midpair_kernel(const float* __restrict__ e)
{
    int bi = blockIdx.x;
    int b = bi / Ll, i = bi % Ll;
    int tid = threadIdx.x;
    int warp = tid >> 5, lane = tid & 31;

    __shared__ __align__(16) float attn_s[NH * Ll];   // 12KB
    __shared__ __align__(16) float pool[4096];        // bias tile (3072), then reduce tree

    // bias tile [j][n]
    {
        const float4* src = (const float4*)&g_bias[(size_t)bi * Ll * NH];
        float4* dst = (float4*)pool;
        for (int m = tid; m < Ll * NH / 4; m += 256) dst[m] = src[m];
    }
    __syncthreads();

    // full logits
    for (int m = tid; m < NH * Ll; m += 256) {
        int n = m / Ll, j = m - n * Ll;
        attn_s[m] = g_logit[((size_t)(b * NH + n) * Ll + i) * Ll + j] + pool[j * NH + n];
    }
    __syncthreads();

    // softmax: warp = head; write normalized attn to smem and g_attn
    {
        float* rowp = &attn_s[warp * Ll];
        float mx = -1e30f;
        for (int j = lane; j < Ll; j += 32) mx = fmaxf(mx, rowp[j]);
        #pragma unroll
        for (int off = 16; off > 0; off >>= 1)
            mx = fmaxf(mx, __shfl_xor_sync(0xffffffffu, mx, off));
        float sum = 0.f;
        for (int j = lane; j < Ll; j += 32) {
            float ex = __expf(rowp[j] - mx);
            rowp[j] = ex;
            sum += ex;
        }
        #pragma unroll
        for (int off = 16; off > 0; off >>= 1)
            sum += __shfl_xor_sync(0xffffffffu, sum, off);
        float inv = 1.f / sum;
        float* ga = &g_attn[(size_t)bi * NH * Ll + warp * Ll];
        for (int j = lane; j < Ll; j += 32) {
            float a = rowp[j] * inv;
            rowp[j] = a;
            ga[j] = a;
        }
    }
    __syncthreads();

    // out_pair = attn @ e : warp owns j-residues, lane owns d-quarter
    float acc[NH][4];
    #pragma unroll
    for (int n = 0; n < NH; n++) { acc[n][0]=0.f; acc[n][1]=0.f; acc[n][2]=0.f; acc[n][3]=0.f; }
    const float4* eb = (const float4*)(e + (size_t)bi * Ll * Dd);
    #pragma unroll 8
    for (int it = 0; it < Ll / 8; it++) {
        int j = warp + it * 8;
        float4 ev = eb[j * 32 + lane];
        #pragma unroll
        for (int n = 0; n < NH; n++) {
            float p = attn_s[n * Ll + j];
            acc[n][0] += p * ev.x; acc[n][1] += p * ev.y;
            acc[n][2] += p * ev.z; acc[n][3] += p * ev.w;
        }
    }
    __syncthreads();   // attn reads done; pool becomes reduce tree

    #pragma unroll
    for (int stride = 4; stride >= 1; stride >>= 1) {
        if (warp >= stride && warp < 2 * stride) {
            float* dstb = &pool[(warp - stride) * 1024];
            #pragma unroll
            for (int n = 0; n < NH; n++)
                *(float4*)&dstb[n * 128 + lane * 4] =
                    make_float4(acc[n][0], acc[n][1], acc[n][2], acc[n][3]);
        }
        __syncthreads();
        if (warp < stride) {
            const float* srcb = &pool[warp * 1024];
            #pragma unroll
            for (int n = 0; n < NH; n++) {
                float4 v = *(const float4*)&srcb[n * 128 + lane * 4];
                acc[n][0] += v.x; acc[n][1] += v.y; acc[n][2] += v.z; acc[n][3] += v.w;
            }
        }
        __syncthreads();
    }
    if (warp == 0) {
        float* feat = &g_feat[bi * FEAT];
        #pragma unroll
        for (int n = 0; n < NH; n++)
            *(float4*)&feat[128 + n * 128 + lane * 4] =
                make_float4(acc[n][0], acc[n][1], acc[n][2], acc[n][3]);
    }
}

// ---------------- kernel 4: out_scalar + op + rotation/norm, grid (16, 6) ----------------
#define IT 64
__global__ __launch_bounds__(224) void sv_kernel(
    const float* __restrict__ r, const float* __restrict__ t)
{
    int bn = blockIdx.x;
    int b = bn >> 3, n = bn & 7;
    int i0 = blockIdx.y * IT;
    int tid = threadIdx.x;
    int ig = tid & 31;        // i-group: rows ig*2, ig*2+1
    int cq = tid >> 5;        // col-quad 0..6 (0-3 scalar d, 4-6 point pc)

    __shared__ __align__(16) float attn_t[64 * IT];   // [j][i], 16KB
    __shared__ __align__(16) float Bsm[64 * 32];      // [j][32] (16 vs + 12 vp + pad), 8KB
    __shared__ __align__(16) float rt_s[IT * 12];     // r(9)+t(3) per i
    __shared__ __align__(16) float op_s[IT * 12];
    __shared__ float opl2[IT * 12];

    for (int m = tid; m < IT * 12; m += 224) {
        int ii = m / 12, c = m % 12;
        rt_s[m] = (c < 9) ? r[(size_t)(b * Ll + i0 + ii) * 9 + c]
                          : t[(size_t)(b * Ll + i0 + ii) * 3 + (c - 9)];
    }

    float a0[4] = {0.f, 0.f, 0.f, 0.f};
    float a1[4] = {0.f, 0.f, 0.f, 0.f};

    for (int c6 = 0; c6 < 6; c6++) {
        int j0 = c6 * 64;
        __syncthreads();
        for (int m = tid; m < IT * 16; m += 224) {
            int ii = m & (IT - 1), jq = m >> 6;
            float4 v = *(const float4*)&g_attn[
                (size_t)(b * Ll + i0 + ii) * (NH * Ll) + n * Ll + j0 + jq * 4];
            attn_t[(jq * 4 + 0) * IT + ii] = v.x;
            attn_t[(jq * 4 + 1) * IT + ii] = v.y;
            attn_t[(jq * 4 + 2) * IT + ii] = v.z;
            attn_t[(jq * 4 + 3) * IT + ii] = v.w;
        }
        for (int m = tid; m < 256; m += 224) {
            int j = m >> 2, dq = m & 3;
            *(float4*)&Bsm[j * 32 + dq * 4] =
                *(const float4*)&g_vs[((size_t)bn * Ll + j0 + j) * DHSc + dq * 4];
        }
        for (int m = tid; m < 192; m += 224) {
            int j = m / 3, dq = m % 3;
            *(float4*)&Bsm[j * 32 + 16 + dq * 4] =
                *(const float4*)&g_vp[((size_t)bn * Ll + j0 + j) * NPC + dq * 4];
        }
        __syncthreads();
        #pragma unroll 4
        for (int j = 0; j < 64; j++) {
            float2 av = *(const float2*)&attn_t[j * IT + ig * 2];
            float4 bv = *(const float4*)&Bsm[j * 32 + cq * 4];
            a0[0] += av.x * bv.x; a0[1] += av.x * bv.y; a0[2] += av.x * bv.z; a0[3] += av.x * bv.w;
            a1[0] += av.y * bv.x; a1[1] += av.y * bv.y; a1[2] += av.y * bv.z; a1[3] += av.y * bv.w;
        }
    }
    __syncthreads();

    if (cq < 4) {
        size_t base0 = (size_t)(b * Ll + i0 + ig * 2) * FEAT + n * DHSc + cq * 4;
        *(float4*)&g_feat[base0]        = make_float4(a0[0], a0[1], a0[2], a0[3]);
        *(float4*)&g_feat[base0 + FEAT] = make_float4(a1[0], a1[1], a1[2], a1[3]);
    } else {
        int pc = (cq - 4) * 4;
        *(float4*)&op_s[(ig * 2 + 0) * 12 + pc] = make_float4(a0[0], a0[1], a0[2], a0[3]);
        *(float4*)&op_s[(ig * 2 + 1) * 12 + pc] = make_float4(a1[0], a1[1], a1[2], a1[3]);
    }
    __syncthreads();

    for (int m = tid; m < IT * 12; m += 224) {
        int ii = m / 12, pc = m % 12;
        int p3 = (pc / 3) * 3, c = pc % 3;
        const float* ob = &op_s[ii * 12 + p3];
        const float* rr = &rt_s[ii * 12];
        float v = (ob[0] - rr[9])  * rr[c * 3 + 0]
                + (ob[1] - rr[10]) * rr[c * 3 + 1]
                + (ob[2] - rr[11]) * rr[c * 3 + 2];
        g_feat[(size_t)(b * Ll + i0 + ii) * FEAT + 1152 + n * 12 + pc] = v;
        opl2[m] = v * v;
    }
    __syncthreads();
    for (int m = tid; m < IT * 4; m += 224) {
        int ii = m >> 2, p = m & 3;
        g_feat[(size_t)(b * Ll + i0 + ii) * FEAT + 1248 + n * 4 + p] =
            sqrtf(opl2[ii * 12 + p * 3] + opl2[ii * 12 + p * 3 + 1] + opl2[ii * 12 + p * 3 + 2]);
    }
}

// ---------------- kernel 5a: partial out GEMM (k-split), 4 rows/thread ----------------
#define TMR 32
#define KC 64
__global__ __launch_bounds__(256) void out_part_kernel(const float* __restrict__ Wo)
{
    int row0 = blockIdx.x * TMR;
    int kbase = blockIdx.y * (FEAT / KSPLIT);
    int tid = threadIdx.x;
    int tx = tid & 31;
    int ty = tid >> 5;       // 0..7 → rows ty*4 .. ty*4+3
    __shared__ __align__(16) float As[TMR * KC];   // 8KB
    __shared__ __align__(16) float Bs[KC * Dd];    // 32KB
    float a0[4] = {0.f,0.f,0.f,0.f};
    float a1[4] = {0.f,0.f,0.f,0.f};
    float a2[4] = {0.f,0.f,0.f,0.f};
    float a3[4] = {0.f,0.f,0.f,0.f};
    #pragma unroll
    for (int tile = 0; tile < (FEAT / KSPLIT) / KC; tile++) {
        int k0 = kbase + tile * KC;
        #pragma unroll
        for (int h = 0; h < 2; h++) {
            int m = tid + h * 256;
            int rr = m >> 4, q = m & 15;
            *(float4*)&As[rr * KC + q * 4] =
                *(const float4*)&g_feat[(row0 + rr) * FEAT + k0 + q * 4];
        }
        {
            const float4* wsrc = (const float4*)(Wo + (size_t)k0 * Dd);
            float4* bdst = (float4*)Bs;
            #pragma unroll
            for (int m = 0; m < 8; m++) bdst[tid + m * 256] = wsrc[tid + m * 256];
        }
        __syncthreads();
        #pragma unroll 4
        for (int kk = 0; kk < KC; kk++) {
            float av0 = As[(ty * 4 + 0) * KC + kk];
            float av1 = As[(ty * 4 + 1) * KC + kk];
            float av2 = As[(ty * 4 + 2) * KC + kk];
            float av3 = As[(ty * 4 + 3) * KC + kk];
            float4 bv = *(const float4*)&Bs[kk * Dd + tx * 4];
            a0[0] += av0 * bv.x; a0[1] += av0 * bv.y; a0[2] += av0 * bv.z; a0[3] += av0 * bv.w;
            a1[0] += av1 * bv.x; a1[1] += av1 * bv.y; a1[2] += av1 * bv.z; a1[3] += av1 * bv.w;
            a2[0] += av2 * bv.x; a2[1] += av2 * bv.y; a2[2] += av2 * bv.z; a2[3] += av2 * bv.w;
            a3[0] += av3 * bv.x; a3[1] += av3 * bv.y; a3[2] += av3 * bv.z; a3[3] += av3 * bv.w;
        }
        __syncthreads();
    }
    size_t base = (size_t)blockIdx.y * OUTROWS * Dd;
    *(float4*)&g_part[base + (size_t)(row0 + ty * 4 + 0) * Dd + tx * 4] =
        make_float4(a0[0], a0[1], a0[2], a0[3]);
    *(float4*)&g_part[base + (size_t)(row0 + ty * 4 + 1) * Dd + tx * 4] =
        make_float4(a1[0], a1[1], a1[2], a1[3]);
    *(float4*)&g_part[base + (size_t)(row0 + ty * 4 + 2) * Dd + tx * 4] =
        make_float4(a2[0], a2[1], a2[2], a2[3]);
    *(float4*)&g_part[base + (size_t)(row0 + ty * 4 + 3) * Dd + tx * 4] =
        make_float4(a3[0], a3[1], a3[2], a3[3]);
}

// ---------------- kernel 5b: reduce partials + bias ----------------
__global__ __launch_bounds__(256) void out_reduce_kernel(
    const float* __restrict__ bo, float* __restrict__ out)
{
    int idx = blockIdx.x * 256 + threadIdx.x;
    int c = idx & (Dd - 1);
    float a = bo[c];
    #pragma unroll
    for (int s = 0; s < KSPLIT; s++) a += g_part[s * (OUTROWS * Dd) + idx];
    out[idx] = a;
}

// ---------------- launch ----------------
extern "C" void kernel_launch(void* const* d_in, const int* in_sizes, int n_in,
                              void* d_out, int out_size) {
    const float* x     = (const float*)d_in[0];
    const float* e     = (const float*)d_in[1];
    const float* r     = (const float*)d_in[2];
    const float* t     = (const float*)d_in[3];
    const float* Wqs   = (const float*)d_in[4];
    const float* Wks   = (const float*)d_in[5];
    const float* Wvs   = (const float*)d_in[6];
    const float* Wb    = (const float*)d_in[7];
    const float* Wqp   = (const float*)d_in[8];
    const float* Wkp   = (const float*)d_in[9];
    const float* Wvp   = (const float*)d_in[10];
    const float* gamma = (const float*)d_in[11];
    const float* Wo    = (const float*)d_in[12];
    const float* bo    = (const float*)d_in[13];
    float* out = (float*)d_out;

    proj_kernel<<<(Bb * Ll) / 8, 256>>>(x, r, t, Wqs, Wks, Wvs, Wqp, Wkp, Wvp);
    qkbias_kernel<<<QKBLKS + (Bb * Ll * Ll) / 256, 256>>>(gamma, e, Wb);
    midpair_kernel<<<Bb * Ll, 256>>>(e);
    sv_kernel<<<dim3(Bb * NH, Ll / IT), 224>>>(r, t);
    out_part_kernel<<<dim3((Bb * Ll) / TMR, KSPLIT), 256>>>(Wo);
    out_reduce_kernel<<<(OUTROWS * Dd) / 256, 256>>>(bo, out);
}